// round 2
// baseline (speedup 1.0000x reference)
#include <cuda_runtime.h>
#include <cstdint>

// ---------------------------------------------------------------------------
// Problem constants (shapes fixed by the dataset)
// ---------------------------------------------------------------------------
static constexpr int B  = 2;
static constexpr int C  = 64;
static constexpr int H1 = 256, W1 = 256;
static constexpr int H2 = 128, W2 = 128;

// ---------------------------------------------------------------------------
// Device scratch (no allocation allowed -> __device__ globals)
// ---------------------------------------------------------------------------
__device__ float g_fea2down[B * 128 * H2 * W2];     // down1 output (128 ch, 128x128)
__device__ float g_fea1    [B * C   * H1 * W1];     // c1 output
__device__ float g_fea2    [B * C   * H2 * W2];     // c12 output
__device__ float g_up1     [B * C   * H1 * W1];     // convT up1
__device__ float g_fea     [B * C   * H1 * W1];     // offset feature (1x1 conv)
__device__ float g_off1    [B * 18  * H1 * W1];     // offsets level 1
__device__ float g_fea11   [B * C   * H1 * W1];     // deform 1 output
__device__ float g_rs2     [B * C   * H2 * W2];     // downrs output
__device__ float g_off2    [B * 18  * H2 * W2];     // offsets level 2
__device__ float g_fea2d   [B * C   * H2 * W2];     // deform 2 output
__device__ float g_up2     [B * C   * H1 * W1];     // convT up2
__device__ float g_wq1     [4 * C * 4 * C];         // repacked up1 weights
__device__ float g_wq2     [4 * C * 4 * C];         // repacked up2 weights

// ---------------------------------------------------------------------------
// Generic direct 3x3 conv, pad=1, stride template.
// Block: 256 threads = 8 rows x 32 cols of output. Each thread accumulates
// CO output channels in registers. Input supplied as two pointers so the
// channel concat never has to be materialized (ci < C0 -> inA else inB).
// ---------------------------------------------------------------------------
template <int STRIDE, int CO>
__global__ __launch_bounds__(256)
void conv3x3_kernel(const float* __restrict__ inA, const float* __restrict__ inB,
                    int C0, int Cin,
                    const float* __restrict__ w, const float* __restrict__ bias,
                    float* __restrict__ out, int Cout,
                    int H, int W, int Ho, int Wo)
{
    constexpr int XR = 7 * STRIDE + 3;                 // input tile rows
    constexpr int XC = 31 * STRIDE + 3;                // input tile cols
    constexpr int XP = XC + (STRIDE == 2 ? 1 : 0);     // padded pitch
    __shared__ __align__(16) float xs[XR * XP];
    __shared__ __align__(16) float w_s[9 * CO];

    const int tid = threadIdx.x;
    const int tx = tid & 31, ty = tid >> 5;
    const int nchunk = (Cout + CO - 1) / CO;
    const int b     = blockIdx.z / nchunk;
    const int chunk = blockIdx.z % nchunk;
    const int co_base = chunk * CO;
    const int ow0 = blockIdx.x * 32;
    const int oh0 = blockIdx.y * 8;
    const int HW = H * W;

    float acc[CO];
#pragma unroll
    for (int o = 0; o < CO; o++) acc[o] = 0.f;

    for (int ci = 0; ci < Cin; ci++) {
        const float* src = (ci < C0)
            ? (inA + ((size_t)b * C0 + ci) * HW)
            : (inB + ((size_t)b * (Cin - C0) + (ci - C0)) * HW);
        __syncthreads();
        // load input tile (zero-padded)
        for (int i = tid; i < XR * XC; i += 256) {
            int lr = i / XC, lc = i % XC;
            int r = oh0 * STRIDE - 1 + lr;
            int c = ow0 * STRIDE - 1 + lc;
            xs[lr * XP + lc] = (r >= 0 && r < H && c >= 0 && c < W) ? src[r * W + c] : 0.f;
        }
        // load weight slice for this ci: w_s[tap][o]
        for (int i = tid; i < 9 * CO; i += 256) {
            int tap = i / CO, o = i % CO;
            int og = co_base + o;
            w_s[tap * CO + o] = (og < Cout) ? w[((size_t)og * Cin + ci) * 9 + tap] : 0.f;
        }
        __syncthreads();

        float xv[9];
#pragma unroll
        for (int kh = 0; kh < 3; kh++)
#pragma unroll
            for (int kw = 0; kw < 3; kw++)
                xv[kh * 3 + kw] = xs[(ty * STRIDE + kh) * XP + tx * STRIDE + kw];

#pragma unroll
        for (int tap = 0; tap < 9; tap++) {
            const float4* w4 = (const float4*)(w_s + tap * CO);
#pragma unroll
            for (int o4 = 0; o4 < CO / 4; o4++) {
                float4 wv = w4[o4];
                acc[o4 * 4 + 0] += xv[tap] * wv.x;
                acc[o4 * 4 + 1] += xv[tap] * wv.y;
                acc[o4 * 4 + 2] += xv[tap] * wv.z;
                acc[o4 * 4 + 3] += xv[tap] * wv.w;
            }
        }
    }

    const int oh = oh0 + ty, ow = ow0 + tx;
    if (oh < Ho && ow < Wo) {
#pragma unroll
        for (int o = 0; o < CO; o++) {
            int og = co_base + o;
            if (og < Cout)
                out[(((size_t)b * Cout + og) * Ho + oh) * Wo + ow] = acc[o] + bias[og];
        }
    }
}

// ---------------------------------------------------------------------------
// Weight repack for transposed conv (4x4, stride 2, pad 1).
// wq[pc][ci][t][o] with pc = pa*2+pb (output parity), t = di*2+dj, and
// kh = 3 - pa - 2*di, kw = 3 - pb - 2*dj.  w layout: (Cin, Cout, 4, 4).
// ---------------------------------------------------------------------------
__global__ void prep_wq_kernel(const float* __restrict__ w, float* __restrict__ wq)
{
    int idx = blockIdx.x * 256 + threadIdx.x;
    if (idx >= 4 * C * 4 * C) return;
    int o  = idx & 63;
    int t  = (idx >> 6) & 3;
    int ci = (idx >> 8) & 63;
    int pc = idx >> 14;
    int pa = pc >> 1, pb = pc & 1;
    int di = t >> 1, dj = t & 1;
    int kh = 3 - pa - 2 * di;
    int kw = 3 - pb - 2 * dj;
    wq[idx] = w[((ci * C + o) * 4 + kh) * 4 + kw];
}

// ---------------------------------------------------------------------------
// Transposed conv 4x4 stride 2 pad 1 (C->C), using repacked weights.
// out[2i+pa, 2j+pb] = bias + sum_ci sum_{di,dj} in[i+pa-1+di, j+pb-1+dj] *
//                       wq[pc][ci][di*2+dj][o]
// Block: 256 threads = 8x32 tile in (i,j) space, blockIdx.z = b*4 + parity.
// ---------------------------------------------------------------------------
__global__ __launch_bounds__(256)
void convt_kernel(const float* __restrict__ in, const float* __restrict__ wq,
                  const float* __restrict__ bias, float* __restrict__ out,
                  int Hin, int Win)
{
    __shared__ __align__(16) float xs[9 * 33];
    __shared__ __align__(16) float w_s[4 * C];

    const int tid = threadIdx.x;
    const int tx = tid & 31, ty = tid >> 5;
    const int zc = blockIdx.z;
    const int b  = zc >> 2;
    const int pc = zc & 3;
    const int pa = pc >> 1, pb = pc & 1;
    const int j0 = blockIdx.x * 32;
    const int i0 = blockIdx.y * 8;
    const int HWin = Hin * Win;
    const float* inb = in + (size_t)b * C * HWin;

    float acc[C];
#pragma unroll
    for (int o = 0; o < C; o++) acc[o] = 0.f;

    for (int ci = 0; ci < C; ci++) {
        __syncthreads();
        for (int i = tid; i < 9 * 33; i += 256) {
            int lr = i / 33, lc = i % 33;
            int r = i0 + pa - 1 + lr;
            int c = j0 + pb - 1 + lc;
            xs[i] = (r >= 0 && r < Hin && c >= 0 && c < Win) ? inb[ci * HWin + r * Win + c] : 0.f;
        }
        // wq slice: 4*64 = 256 floats, exactly one per thread
        w_s[tid] = wq[((size_t)pc * C + ci) * (4 * C) + tid];
        __syncthreads();

        float xv[4];
#pragma unroll
        for (int di = 0; di < 2; di++)
#pragma unroll
            for (int dj = 0; dj < 2; dj++)
                xv[di * 2 + dj] = xs[(ty + di) * 33 + tx + dj];

#pragma unroll
        for (int t = 0; t < 4; t++) {
            const float4* w4 = (const float4*)(w_s + t * C);
#pragma unroll
            for (int o4 = 0; o4 < C / 4; o4++) {
                float4 wv = w4[o4];
                acc[o4 * 4 + 0] += xv[t] * wv.x;
                acc[o4 * 4 + 1] += xv[t] * wv.y;
                acc[o4 * 4 + 2] += xv[t] * wv.z;
                acc[o4 * 4 + 3] += xv[t] * wv.w;
            }
        }
    }

    const int oh = 2 * (i0 + ty) + pa;
    const int ow = 2 * (j0 + tx) + pb;
    const int Hout = 2 * Hin, Wout = 2 * Win;
#pragma unroll
    for (int o = 0; o < C; o++)
        out[(((size_t)b * C + o) * Hout + oh) * Wout + ow] = acc[o] + bias[o];
}

// ---------------------------------------------------------------------------
// 1x1 conv over (a + b2), C->C. One thread per pixel, 64 accumulators.
// ---------------------------------------------------------------------------
__global__ __launch_bounds__(256)
void conv1x1_add_kernel(const float* __restrict__ a, const float* __restrict__ b2,
                        const float* __restrict__ w, const float* __restrict__ bias,
                        float* __restrict__ out, int HW)
{
    __shared__ __align__(16) float w_s[C * C];   // [ci][o]
    const int tid = threadIdx.x;
    for (int i = tid; i < C * C; i += 256) {
        int ci = i >> 6, o = i & 63;
        w_s[i] = w[o * C + ci];
    }
    __syncthreads();

    const int pix = blockIdx.x * 256 + tid;
    const int b = blockIdx.y;
    if (pix >= HW) return;
    const float* ab = a  + (size_t)b * C * HW + pix;
    const float* bb = b2 + (size_t)b * C * HW + pix;

    float acc[C];
#pragma unroll
    for (int o = 0; o < C; o++) acc[o] = 0.f;

    for (int ci = 0; ci < C; ci++) {
        float xv = ab[(size_t)ci * HW] + bb[(size_t)ci * HW];
        const float4* w4 = (const float4*)(w_s + ci * C);
#pragma unroll
        for (int o4 = 0; o4 < C / 4; o4++) {
            float4 wv = w4[o4];
            acc[o4 * 4 + 0] += xv * wv.x;
            acc[o4 * 4 + 1] += xv * wv.y;
            acc[o4 * 4 + 2] += xv * wv.z;
            acc[o4 * 4 + 3] += xv * wv.w;
        }
    }
    float* ob = out + (size_t)b * C * HW + pix;
#pragma unroll
    for (int o = 0; o < C; o++)
        ob[(size_t)o * HW] = acc[o] + bias[o];
}

// ---------------------------------------------------------------------------
// Deformable conv (ks=3, pad=1, C->C), matching the reference semantics:
//   pr = h + 1 + (n/3 - 1) + off_r[b,n,h,w], clipped to [0, H+1]
//   bilinear gather from the zero-padded image, then
//   out[o] = bias[o] + sum_{c,n} v[c][n] * w[o, c, n]
// One thread per output pixel; per-tap 64x64 weight slice in SMEM.
// ---------------------------------------------------------------------------
__global__ __launch_bounds__(256)
void deform_kernel(const float* __restrict__ x, const float* __restrict__ off,
                   const float* __restrict__ w, const float* __restrict__ bias,
                   float* __restrict__ out, int H, int W)
{
    __shared__ __align__(16) float w_s[C * C];   // [c][o] for the current tap
    const int tid = threadIdx.x;
    const int tx = tid & 31, ty = tid >> 5;
    const int ow = blockIdx.x * 32 + tx;
    const int oh = blockIdx.y * 8 + ty;
    const int b  = blockIdx.z;
    const int HW = H * W;
    const float* xb   = x   + (size_t)b * C * HW;
    const float* offb = off + (size_t)b * 18 * HW;
    const int pix = oh * W + ow;

    float acc[C];
#pragma unroll
    for (int o = 0; o < C; o++) acc[o] = 0.f;

    const float rmax = (float)(H + 1);   // Hp - 1
    const float cmax = (float)(W + 1);   // Wp - 1

    for (int n = 0; n < 9; n++) {
        __syncthreads();
        for (int i = tid; i < C * C; i += 256) {
            int c = i >> 6, o = i & 63;
            w_s[i] = w[(size_t)o * (C * 9) + c * 9 + n];
        }
        __syncthreads();

        float offr = offb[(size_t)n * HW + pix];
        float offc = offb[(size_t)(9 + n) * HW + pix];
        float pr = (float)(oh + (n / 3)) + offr;       // oh + 1 + (n/3 - 1)
        float pcc = (float)(ow + (n % 3)) + offc;
        pr  = fminf(fmaxf(pr, 0.f), rmax);
        pcc = fminf(fmaxf(pcc, 0.f), cmax);
        float r0f = floorf(pr), c0f = floorf(pcc);
        int r0 = (int)r0f, c0 = (int)c0f;
        int r1 = min(r0 + 1, H + 1), c1 = min(c0 + 1, W + 1);
        float fr = pr - r0f, fc = pcc - c0f;
        float w00 = (1.f - fr) * (1.f - fc);
        float w01 = (1.f - fr) * fc;
        float w10 = fr * (1.f - fc);
        float w11 = fr * fc;

        // padded -> unpadded coords with validity masks folded into weights
        int rr0 = r0 - 1, rr1 = r1 - 1, cc0 = c0 - 1, cc1 = c1 - 1;
        bool vr0 = (rr0 >= 0) && (rr0 < H);
        bool vr1 = (rr1 >= 0) && (rr1 < H);
        bool vc0 = (cc0 >= 0) && (cc0 < W);
        bool vc1 = (cc1 >= 0) && (cc1 < W);
        float m00 = (vr0 && vc0) ? w00 : 0.f;
        float m01 = (vr0 && vc1) ? w01 : 0.f;
        float m10 = (vr1 && vc0) ? w10 : 0.f;
        float m11 = (vr1 && vc1) ? w11 : 0.f;
        int sr0 = vr0 ? rr0 : 0, sr1 = vr1 ? rr1 : 0;
        int sc0 = vc0 ? cc0 : 0, sc1 = vc1 ? cc1 : 0;
        int i00 = sr0 * W + sc0;
        int i01 = sr0 * W + sc1;
        int i10 = sr1 * W + sc0;
        int i11 = sr1 * W + sc1;

        for (int c = 0; c < C; c++) {
            const float* xc = xb + (size_t)c * HW;
            float v = m00 * xc[i00] + m01 * xc[i01] + m10 * xc[i10] + m11 * xc[i11];
            const float4* w4 = (const float4*)(w_s + c * C);
#pragma unroll
            for (int o4 = 0; o4 < C / 4; o4++) {
                float4 wv = w4[o4];
                acc[o4 * 4 + 0] += v * wv.x;
                acc[o4 * 4 + 1] += v * wv.y;
                acc[o4 * 4 + 2] += v * wv.z;
                acc[o4 * 4 + 3] += v * wv.w;
            }
        }
    }

    if (oh < H && ow < W) {
#pragma unroll
        for (int o = 0; o < C; o++)
            out[(((size_t)b * C + o) * H + oh) * W + ow] = acc[o] + bias[o];
    }
}

// ---------------------------------------------------------------------------
// Launch. Symbol addresses are cached in function-statics on the FIRST call
// (the harness's correctness run), so the graph-capture call performs kernel
// launches only — no runtime API calls during capture.
// ---------------------------------------------------------------------------
static float* sym(const void* s)
{
    void* p = nullptr;
    cudaGetSymbolAddress(&p, s);
    return (float*)p;
}

extern "C" void kernel_launch(void* const* d_in, const int* in_sizes, int n_in,
                              void* d_out, int out_size)
{
    const float* dem      = (const float*)d_in[0];
    const float* rs       = (const float*)d_in[1];
    const float* w_down1  = (const float*)d_in[2];
    const float* b_down1  = (const float*)d_in[3];
    const float* w_c1     = (const float*)d_in[4];
    const float* b_c1     = (const float*)d_in[5];
    const float* w_c12    = (const float*)d_in[6];
    const float* b_c12    = (const float*)d_in[7];
    const float* w_up1    = (const float*)d_in[8];
    const float* b_up1    = (const float*)d_in[9];
    const float* w_downrs = (const float*)d_in[10];
    const float* b_downrs = (const float*)d_in[11];
    const float* w_off    = (const float*)d_in[12];
    const float* b_off    = (const float*)d_in[13];
    const float* w_c3     = (const float*)d_in[14];
    const float* b_c3     = (const float*)d_in[15];
    const float* w_d1o    = (const float*)d_in[16];
    const float* b_d1o    = (const float*)d_in[17];
    const float* w_d1     = (const float*)d_in[18];
    const float* b_d1     = (const float*)d_in[19];
    const float* w_d2o    = (const float*)d_in[20];
    const float* b_d2o    = (const float*)d_in[21];
    const float* w_d2     = (const float*)d_in[22];
    const float* b_d2     = (const float*)d_in[23];
    const float* w_up2    = (const float*)d_in[24];
    const float* b_up2    = (const float*)d_in[25];
    float* outp = (float*)d_out;

    // One-time symbol address resolution (first call = correctness run).
    static float* fea2down = sym(g_fea2down);
    static float* fea1     = sym(g_fea1);
    static float* fea2     = sym(g_fea2);
    static float* up1      = sym(g_up1);
    static float* fea      = sym(g_fea);
    static float* off1     = sym(g_off1);
    static float* fea11    = sym(g_fea11);
    static float* rs2      = sym(g_rs2);
    static float* off2     = sym(g_off2);
    static float* fea2d    = sym(g_fea2d);
    static float* up2      = sym(g_up2);
    static float* wq1      = sym(g_wq1);
    static float* wq2      = sym(g_wq2);

    dim3 blk(256);

    // 1) fea_2 = conv(cat, w_down1, s=2) : (B,128,128,128)
    conv3x3_kernel<2, 64><<<dim3(W2 / 32, H2 / 8, B * 2), blk>>>(
        dem, rs, C, 2 * C, w_down1, b_down1, fea2down, 2 * C, H1, W1, H2, W2);

    // 2) fea_1 = conv(cat, w_c1, s=1) : (B,64,256,256)
    conv3x3_kernel<1, 64><<<dim3(W1 / 32, H1 / 8, B), blk>>>(
        dem, rs, C, 2 * C, w_c1, b_c1, fea1, C, H1, W1, H1, W1);

    // 3) fea_2 = conv(fea_2, w_c12, s=1) : (B,64,128,128)
    conv3x3_kernel<1, 64><<<dim3(W2 / 32, H2 / 8, B), blk>>>(
        fea2down, fea2down, 2 * C, 2 * C, w_c12, b_c12, fea2, C, H2, W2, H2, W2);

    // 4) fea_2_1 = convT(fea_2, w_up1) : (B,64,256,256)
    prep_wq_kernel<<<dim3((4 * C * 4 * C + 255) / 256), blk>>>(w_up1, wq1);
    convt_kernel<<<dim3(W2 / 32, H2 / 8, B * 4), blk>>>(fea2, wq1, b_up1, up1, H2, W2);

    // 5) fea = 1x1 conv(fea_1 + fea_2_1, w_off)
    conv1x1_add_kernel<<<dim3((H1 * W1) / 256, B), blk>>>(fea1, up1, w_off, b_off, fea, H1 * W1);

    // 6) offsets level 1 = conv(fea, w_d1o) : (B,18,256,256)
    conv3x3_kernel<1, 20><<<dim3(W1 / 32, H1 / 8, B), blk>>>(
        fea, fea, C, C, w_d1o, b_d1o, off1, 18, H1, W1, H1, W1);

    // 7) fea_1_1 = deform(rs, off1, w_d1)
    deform_kernel<<<dim3(W1 / 32, H1 / 8, B), blk>>>(rs, off1, w_d1, b_d1, fea11, H1, W1);

    // 8) rs_2 = conv(rs, w_downrs, s=2) : (B,64,128,128)
    conv3x3_kernel<2, 64><<<dim3(W2 / 32, H2 / 8, B), blk>>>(
        rs, rs, C, C, w_downrs, b_downrs, rs2, C, H1, W1, H2, W2);

    // 9) offsets level 2 = conv(fea_2, w_d2o) : (B,18,128,128)
    conv3x3_kernel<1, 20><<<dim3(W2 / 32, H2 / 8, B), blk>>>(
        fea2, fea2, C, C, w_d2o, b_d2o, off2, 18, H2, W2, H2, W2);

    // 10) fea_2 = deform(rs_2, off2, w_d2)
    deform_kernel<<<dim3(W2 / 32, H2 / 8, B), blk>>>(rs2, off2, w_d2, b_d2, fea2d, H2, W2);

    // 11) fea_2_1 = convT(fea_2, w_up2) : (B,64,256,256)
    prep_wq_kernel<<<dim3((4 * C * 4 * C + 255) / 256), blk>>>(w_up2, wq2);
    convt_kernel<<<dim3(W2 / 32, H2 / 8, B * 4), blk>>>(fea2d, wq2, b_up2, up2, H2, W2);

    // 12) out = 1x1 conv(fea_1_1 + fea_2_1, w_c3)
    conv1x1_add_kernel<<<dim3((H1 * W1) / 256, B), blk>>>(fea11, up2, w_c3, b_c3, outp, H1 * W1);
}